// round 3
// baseline (speedup 1.0000x reference)
#include <cuda_runtime.h>

#define NPT 49    // N+1 render sdist points
#define NW  48    // N render weights
#define PB  98    // 2N+2 blur bounds
#define P0  257   // prop level 0 sdist points
#define P1  97    // prop level 1 sdist points

// accumulators: [0]=rgb, [1]=inter0, [2]=inter1, [3]=dist, [4]=hash0, [5]=hash1
__device__ double g_acc[6];

__global__ void zero_kernel() {
    if (threadIdx.x < 6) g_acc[threadIdx.x] = 0.0;
}

// Exact replication of sorted_interp_quad per-query semantics (incl. argmax/argmin
// first-occurrence tie rules on flat CDF regions).
__device__ __forceinline__ float interp_q(float x, const float* __restrict__ xp,
                                          const float* __restrict__ fpdf,
                                          const float* __restrict__ fcdf) {
    const int P = PB;
    // pl = last index with xp[p] <= x, or -1
    int lo = 0, hi = P;
    while (lo < hi) { int m = (lo + hi) >> 1; if (xp[m] <= x) lo = m + 1; else hi = m; }
    int pl = lo - 1;

    float xp0, xp1, f0, f1;
    int i0, i1;
    if (pl < 0) {
        xp0 = xp[0]; f0 = fcdf[0]; i0 = 0;
    } else {
        xp0 = xp[pl]; f0 = fcdf[pl];
        // i0 = first p in [0,pl] with fcdf[p] == f0 (fcdf non-decreasing)
        int a = 0, b = pl;
        while (a < b) { int m = (a + b) >> 1; if (fcdf[m] < f0) a = m + 1; else b = m; }
        i0 = a;
    }
    if (pl == P - 1) {
        xp1 = xp[P - 1]; f1 = fcdf[P - 1]; i1 = 0;
    } else {
        int pf = pl + 1;
        xp1 = xp[pf]; f1 = fcdf[pf];
        i1 = (pl >= 0 && fcdf[P - 1] == f1) ? 0 : pf;
    }
    float fp0 = fpdf[i0], fp1 = fpdf[i1];
    float num = x - xp0, den = xp1 - xp0;
    float off;
    if (den != 0.0f) off = num / den;
    else             off = (num > 0.0f) ? 1.0f : 0.0f;  // matches nan_to_num(+/-inf,nan)+clip
    off = fminf(fmaxf(off, 0.0f), 1.0f);
    return f0 + num * (fp0 + fp1 * off + fp0 * (1.0f - off)) * 0.5f;
}

__global__ __launch_bounds__(256) void ray_kernel(
    const float* __restrict__ pd, const float* __restrict__ gt,
    const float* __restrict__ sdist, const float* __restrict__ wts,
    const float* __restrict__ ps0, const float* __restrict__ pw0,
    const float* __restrict__ ps1, const float* __restrict__ pw1) {
    __shared__ float s_s[NPT], s_w[NW], s_wn[NW];
    __shared__ float bnd[2][PB], wbm[2][PB], cdfm[2][PB];
    __shared__ float itp0[P0], itp1[P1];
    __shared__ float s_part[4];  // rgb, i0, i1, dist

    const int r = blockIdx.x;
    const int t = threadIdx.x;

    if (t < 4) s_part[t] = 0.0f;
    if (t < NPT) s_s[t] = sdist[r * NPT + t];
    if (t < NW)  s_w[t] = wts[r * NW + t];
    __syncthreads();
    if (t < NW) s_wn[t] = s_w[t] / (s_s[t + 1] - s_s[t] + 1e-8f);
    __syncthreads();

    // ---- blur_step_function prep: lane 0 of warp 0 (pw=0.01) and warp 1 (pw=0.005) ----
    if (t == 0 || t == 32) {
        const int lvl = t >> 5;
        const float pw = (lvl == 0) ? 0.01f : 0.005f;
        const float two_pw = 2.0f * pw;
        float* B = bnd[lvl]; float* W = wbm[lvl]; float* C = cdfm[lvl];
        int ia = 0, ib = 0;
        float crun = 0.0f, srun = 0.0f, acc = 0.0f, prev = 0.0f, wprev = 0.0f;
        W[0] = 0.0f; C[0] = 0.0f;
        #pragma unroll 1
        for (int k = 0; k < PB; k++) {
            float av = (ia < NPT) ? (s_s[ia] - pw) : 3.0e38f;
            float bv = (ib < NPT) ? (s_s[ib] + pw) : 3.0e38f;
            float val, rdv;
            if (av <= bv) {  // stable merge: first half wins ties (matches stable argsort)
                float d = ((ia < NW) ? s_wn[ia] : 0.0f) - ((ia > 0) ? s_wn[ia - 1] : 0.0f);
                rdv = d / two_pw; val = av; ia++;
            } else {
                float d = ((ib < NW) ? s_wn[ib] : 0.0f) - ((ib > 0) ? s_wn[ib - 1] : 0.0f);
                rdv = -d / two_pw; val = bv; ib++;
            }
            B[k] = val;
            if (k > 0) {
                float ds = val - prev;
                srun += ds * crun;             // cumsum(ds * cumsum(radio_sorted))
                float wk = fmaxf(srun, 0.0f);  // elementwise max with 0 (non-feedback)
                W[k] = wk;
                acc += 0.5f * (wk + wprev) * ds;
                C[k] = acc;
                wprev = wk;
            }
            crun += rdv;
            prev = val;
        }
    }

    // ---- distortion loss (concurrent with prep, warps 2..3) ----
    float pdist = 0.0f;
    if (t >= 64 && t < 64 + NW) {
        int n = t - 64;
        float midn = 0.5f * (s_s[n + 1] + s_s[n]);
        float inner = 0.0f;
        #pragma unroll
        for (int m = 0; m < NW; m++) {
            float midm = 0.5f * (s_s[m + 1] + s_s[m]);
            inner += s_w[m] * fabsf(midn - midm);
        }
        float ds = s_s[n + 1] - s_s[n];
        pdist = s_w[n] * inner + s_w[n] * s_w[n] * ds * (1.0f / 3.0f);
    }

    // ---- rgb loss (3 channels of this ray) ----
    float prgb = 0.0f;
    if (t < 3) { float d = pd[r * 3 + t] - gt[r * 3 + t]; prgb = d * d; }

    __syncthreads();  // blur tables ready

    // ---- sorted_interp_quad queries ----
    for (int q = t; q < P0; q += 256)
        itp0[q] = interp_q(ps0[r * P0 + q], bnd[0], wbm[0], cdfm[0]);
    for (int q = t; q < P1; q += 256)
        itp1[q] = interp_q(ps1[r * P1 + q], bnd[1], wbm[1], cdfm[1]);
    __syncthreads();

    float li0 = 0.0f, li1 = 0.0f;
    for (int q = t; q < P0 - 1; q += 256) {
        float ws  = itp0[q + 1] - itp0[q];
        float pwv = pw0[r * (P0 - 1) + q];
        float d = fmaxf(ws - pwv, 0.0f);
        li0 += d * d / (pwv + 1e-5f);
    }
    for (int q = t; q < P1 - 1; q += 256) {
        float ws  = itp1[q + 1] - itp1[q];
        float pwv = pw1[r * (P1 - 1) + q];
        float d = fmaxf(ws - pwv, 0.0f);
        li1 += d * d / (pwv + 1e-5f);
    }

    // ---- block reduce 4 values ----
    #pragma unroll
    for (int o = 16; o > 0; o >>= 1) {
        prgb  += __shfl_down_sync(0xffffffffu, prgb,  o);
        li0   += __shfl_down_sync(0xffffffffu, li0,   o);
        li1   += __shfl_down_sync(0xffffffffu, li1,   o);
        pdist += __shfl_down_sync(0xffffffffu, pdist, o);
    }
    if ((t & 31) == 0) {
        atomicAdd(&s_part[0], prgb);
        atomicAdd(&s_part[1], li0);
        atomicAdd(&s_part[2], li1);
        atomicAdd(&s_part[3], pdist);
    }
    __syncthreads();
    if (t == 0) {
        atomicAdd(&g_acc[0], (double)s_part[0]);
        atomicAdd(&g_acc[1], (double)s_part[1]);
        atomicAdd(&g_acc[2], (double)s_part[2]);
        atomicAdd(&g_acc[3], (double)s_part[3]);
    }
}

__global__ __launch_bounds__(256) void hash_kernel(
    const float* __restrict__ e0, const float* __restrict__ e1,
    const int* __restrict__ ix0, const int* __restrict__ ix1, int M) {
    __shared__ float s_p[2];
    const int t = threadIdx.x;
    if (t < 2) s_p[t] = 0.0f;
    __syncthreads();

    int g = blockIdx.x * blockDim.x + t;
    float c0 = 0.0f, c1 = 0.0f;
    if (g < M) {
        {
            int v = ix0[g];
            int lo = 0, hi = g + 1;               // lower_bound in [0, g]
            while (lo < hi) { int m = (lo + hi) >> 1; if (ix0[m] < v) lo = m + 1; else hi = m; }
            int lb = lo;
            lo = g + 1; hi = M;                   // upper_bound in (g, M]
            while (lo < hi) { int m = (lo + hi) >> 1; if (ix0[m] <= v) lo = m + 1; else hi = m; }
            int cnt = lo - lb;
            float a = e0[2 * g], b = e0[2 * g + 1];
            c0 = (a * a + b * b) / (float)cnt;
        }
        {
            int v = ix1[g];
            int lo = 0, hi = g + 1;
            while (lo < hi) { int m = (lo + hi) >> 1; if (ix1[m] < v) lo = m + 1; else hi = m; }
            int lb = lo;
            lo = g + 1; hi = M;
            while (lo < hi) { int m = (lo + hi) >> 1; if (ix1[m] <= v) lo = m + 1; else hi = m; }
            int cnt = lo - lb;
            float a = e1[2 * g], b = e1[2 * g + 1];
            c1 = (a * a + b * b) / (float)cnt;
        }
    }
    #pragma unroll
    for (int o = 16; o > 0; o >>= 1) {
        c0 += __shfl_down_sync(0xffffffffu, c0, o);
        c1 += __shfl_down_sync(0xffffffffu, c1, o);
    }
    if ((t & 31) == 0) {
        atomicAdd(&s_p[0], c0);
        atomicAdd(&s_p[1], c1);
    }
    __syncthreads();
    if (t == 0) {
        atomicAdd(&g_acc[4], (double)s_p[0]);
        atomicAdd(&g_acc[5], (double)s_p[1]);
    }
}

__global__ void final_kernel(float* out, int R) {
    // W_RGB=1, W_INTER=1, W_DIST=0.01, W_HASH=0.1
    double loss =
        g_acc[0] / ((double)R * 3.0)
      + g_acc[1] / ((double)R * 256.0)
      + g_acc[2] / ((double)R * 96.0)
      + 0.01 * g_acc[3] / (double)R
      + 0.1 * (g_acc[4] + g_acc[5]) / (65536.0 * 2.0);
    out[0] = (float)loss;
}

extern "C" void kernel_launch(void* const* d_in, const int* in_sizes, int n_in,
                              void* d_out, int out_size) {
    const float* pd    = (const float*)d_in[0];
    const float* gt    = (const float*)d_in[1];
    const float* sdist = (const float*)d_in[2];
    const float* wts   = (const float*)d_in[3];
    const float* ps0   = (const float*)d_in[4];
    const float* pw0   = (const float*)d_in[5];
    const float* ps1   = (const float*)d_in[6];
    const float* pw1   = (const float*)d_in[7];
    const float* e0    = (const float*)d_in[8];
    const float* e1    = (const float*)d_in[9];
    const int*   ix0   = (const int*)d_in[10];
    const int*   ix1   = (const int*)d_in[11];

    int R = in_sizes[0] / 3;        // 4096
    int M = in_sizes[8] / 2;        // 196608

    zero_kernel<<<1, 32>>>();
    ray_kernel<<<R, 256>>>(pd, gt, sdist, wts, ps0, pw0, ps1, pw1);
    hash_kernel<<<(M + 255) / 256, 256>>>(e0, e1, ix0, ix1, M);
    final_kernel<<<1, 1>>>((float*)d_out, R);
}

// round 4
// speedup vs baseline: 3.0051x; 3.0051x over previous
#include <cuda_runtime.h>

#define NPT 49    // N+1 render sdist points
#define NW  48    // N render weights
#define PB  98    // 2N+2 blur bounds
#define P0  257   // prop level 0 sdist points
#define P1  97    // prop level 1 sdist points

// accumulators: [0]=rgb, [1]=inter0, [2]=inter1, [3]=dist, [4]=hash0, [5]=hash1
__device__ double g_acc[6];          // zero-initialized at module load; reset by finalizer
__device__ unsigned int g_ticket;    // ditto

__device__ __forceinline__ float wexscan_add(float v, int lane) {
    float x = v;
#pragma unroll
    for (int o = 1; o < 32; o <<= 1) {
        float y = __shfl_up_sync(0xffffffffu, x, o);
        if (lane >= o) x += y;
    }
    return x - v;  // exclusive prefix
}

// inclusive in-place +scan of a[0..97] by one warp (4 contiguous elems per lane)
__device__ __forceinline__ void iscan98(float* a, int lane) {
    const int base = lane << 2;
    float v[4];
#pragma unroll
    for (int i = 0; i < 4; i++) { int k = base + i; v[i] = (k < PB) ? a[k] : 0.0f; }
    float s = 0.0f;
#pragma unroll
    for (int i = 0; i < 4; i++) { s += v[i]; v[i] = s; }
    float off = wexscan_add(s, lane);
#pragma unroll
    for (int i = 0; i < 4; i++) { int k = base + i; if (k < PB) a[k] = v[i] + off; }
    __syncwarp();
}

// inclusive in-place max-scan of int a[0..97] by one warp (identity 0; values >= 0)
__device__ __forceinline__ void imaxscan98(int* a, int lane) {
    const int base = lane << 2;
    int v[4];
#pragma unroll
    for (int i = 0; i < 4; i++) { int k = base + i; v[i] = (k < PB) ? a[k] : 0; }
    int loc = 0;
#pragma unroll
    for (int i = 0; i < 4; i++) { loc = max(loc, v[i]); v[i] = loc; }
    int inc = loc;
#pragma unroll
    for (int o = 1; o < 32; o <<= 1) {
        int y = __shfl_up_sync(0xffffffffu, inc, o);
        if (lane >= o) inc = max(inc, y);
    }
    int exc = __shfl_up_sync(0xffffffffu, inc, 1);
    if (lane == 0) exc = 0;
#pragma unroll
    for (int i = 0; i < 4; i++) { int k = base + i; if (k < PB) a[k] = max(v[i], exc); }
    __syncwarp();
}

// sorted_interp_quad per-query semantics; i0 tie-search replaced by precomputed FF[]
__device__ __forceinline__ float interp_q(float x, const float* __restrict__ B,
                                          const float* __restrict__ W,
                                          const float* __restrict__ C,
                                          const int* __restrict__ FF) {
    int lo = 0, hi = PB;
    while (lo < hi) { int m = (lo + hi) >> 1; if (B[m] <= x) lo = m + 1; else hi = m; }
    int pl = lo - 1;
    float xp0, f0, fp0;
    if (pl < 0) { xp0 = B[0]; f0 = C[0]; fp0 = W[0]; }
    else { xp0 = B[pl]; f0 = C[pl]; fp0 = W[FF[pl]]; }
    float xp1, fp1;
    if (pl == PB - 1) { xp1 = B[PB - 1]; fp1 = W[0]; }
    else {
        int pf = pl + 1;
        xp1 = B[pf];
        fp1 = (pl >= 0 && C[PB - 1] == C[pf]) ? W[0] : W[pf];
    }
    float num = x - xp0, den = xp1 - xp0;
    float off = (den != 0.0f) ? num / den : ((num > 0.0f) ? 1.0f : 0.0f);
    off = fminf(fmaxf(off, 0.0f), 1.0f);
    return f0 + num * (fp0 + fp1 * off + fp0 * (1.0f - off)) * 0.5f;
}

__global__ __launch_bounds__(256) void fused_kernel(
    const float* __restrict__ pd, const float* __restrict__ gt,
    const float* __restrict__ sdist, const float* __restrict__ wts,
    const float* __restrict__ ps0, const float* __restrict__ pw0,
    const float* __restrict__ ps1, const float* __restrict__ pw1,
    const float* __restrict__ e0, const float* __restrict__ e1,
    const int* __restrict__ ix0, const int* __restrict__ ix1,
    int R, int M, int HB, float* __restrict__ out)
{
    __shared__ float s_s[NPT], s_w[NW], s_wn[NW];
    __shared__ float Bb[2][PB], Wb[2][PB], Cb[2][PB], Tb[2][PB];
    __shared__ int   FFb[2][PB];
    __shared__ float itp0[P0], itp1[P1];
    __shared__ float s_part[4];

    const int bid = blockIdx.x;
    const int t = threadIdx.x;
    const int lane = t & 31;
    const int wid = t >> 5;

    if (t < 4) s_part[t] = 0.0f;

    if (bid < HB) {
        // ───────────────── hash decay: run-scan over sorted indices ─────────────────
        int g = bid * 256 + t;
        float c0 = 0.0f, c1 = 0.0f;
        if (g < M) {
            int v = ix0[g];
            if (g == 0 || ix0[g - 1] != v) {      // run start owns the whole run
                float sum = 0.0f; int cnt = 0; int j = g;
                while (j < M && ix0[j] == v) {
                    float2 e = reinterpret_cast<const float2*>(e0)[j];
                    sum += e.x * e.x + e.y * e.y; cnt++; j++;
                }
                c0 = sum / (float)cnt;
            }
            v = ix1[g];
            if (g == 0 || ix1[g - 1] != v) {
                float sum = 0.0f; int cnt = 0; int j = g;
                while (j < M && ix1[j] == v) {
                    float2 e = reinterpret_cast<const float2*>(e1)[j];
                    sum += e.x * e.x + e.y * e.y; cnt++; j++;
                }
                c1 = sum / (float)cnt;
            }
        }
#pragma unroll
        for (int o = 16; o > 0; o >>= 1) {
            c0 += __shfl_down_sync(0xffffffffu, c0, o);
            c1 += __shfl_down_sync(0xffffffffu, c1, o);
        }
        __syncthreads();
        if (lane == 0) { atomicAdd(&s_part[0], c0); atomicAdd(&s_part[1], c1); }
        __syncthreads();
        if (t == 0) {
            atomicAdd(&g_acc[4], (double)s_part[0]);
            atomicAdd(&g_acc[5], (double)s_part[1]);
        }
    } else {
        // ───────────────── per-ray losses ─────────────────
        const int r = bid - HB;
        if (t < NPT) s_s[t] = sdist[r * NPT + t];
        if (t < NW)  s_w[t] = wts[r * NW + t];
        __syncthreads();
        if (t < NW) s_wn[t] = s_w[t] / (s_s[t + 1] - s_s[t] + 1e-8f);
        __syncthreads();

        float pdist = 0.0f, prgb = 0.0f;
        if (wid < 2) {
            // blur_step_function + CDF, one warp per pulse level, fully parallel.
            const int lvl = wid;
            const float pw = lvl ? 0.005f : 0.01f;
            const float inv2 = 1.0f / (2.0f * pw);
            float* B = Bb[lvl]; float* T = Tb[lvl]; float* W = Wb[lvl];
            float* C = Cb[lvl]; int* FF = FFb[lvl];

            // scatter by stable-merge rank. Comparisons use the exact sort-key
            // expressions (s+pw vs s-pw) so the two rank rules are complements.
#pragma unroll
            for (int rep = 0; rep < 2; rep++) {
                int i = lane + rep * 32;
                if (i < NPT) {
                    float si = s_s[i];
                    float d = ((i < NW) ? s_wn[i] : 0.0f) - ((i > 0) ? s_wn[i - 1] : 0.0f);
                    float rd = d * inv2;
                    float av = si - pw;                        // A element
                    int lo = 0, hi = NPT;                       // #B strictly before
                    while (lo < hi) { int m = (lo + hi) >> 1; if (s_s[m] + pw < av) lo = m + 1; else hi = m; }
                    int ra = i + lo;
                    B[ra] = av; T[ra] = rd;
                    float bv = si + pw;                        // B element
                    lo = 0; hi = NPT;                           // #A at-or-before
                    while (lo < hi) { int m = (lo + hi) >> 1; if (s_s[m] - pw <= bv) lo = m + 1; else hi = m; }
                    int rb = i + lo;
                    B[rb] = bv; T[rb] = -rd;
                }
            }
            __syncwarp();
            iscan98(T, lane);                       // c = cumsum(radio_sorted)
            {
                const int base = lane << 2;
#pragma unroll
                for (int i2 = 0; i2 < 4; i2++) {
                    int k = base + i2;
                    if (k < PB - 1) T[k] = (B[k + 1] - B[k]) * T[k];
                    else if (k == PB - 1) T[k] = 0.0f;
                }
            }
            __syncwarp();
            iscan98(T, lane);                       // r = cumsum(ds * c)
            {
                const int base = lane << 2;
#pragma unroll
                for (int i2 = 0; i2 < 4; i2++) {
                    int k = base + i2;
                    if (k < PB) W[k] = (k == 0) ? 0.0f : fmaxf(T[k - 1], 0.0f);
                }
            }
            __syncwarp();
            {
                const int base = lane << 2;
#pragma unroll
                for (int i2 = 0; i2 < 4; i2++) {
                    int k = base + i2;
                    if (k < PB - 1) T[k] = 0.5f * (W[k + 1] + W[k]) * (B[k + 1] - B[k]);
                    else if (k == PB - 1) T[k] = 0.0f;
                }
            }
            __syncwarp();
            iscan98(T, lane);                       // cumulative trapezoid area
            {
                const int base = lane << 2;
#pragma unroll
                for (int i2 = 0; i2 < 4; i2++) {
                    int k = base + i2;
                    if (k < PB) C[k] = (k == 0) ? 0.0f : T[k - 1];
                }
            }
            __syncwarp();
            {
                const int base = lane << 2;
#pragma unroll
                for (int i2 = 0; i2 < 4; i2++) {
                    int k = base + i2;
                    if (k < PB) FF[k] = (k == 0 || C[k] != C[k - 1]) ? k : 0;
                }
            }
            __syncwarp();
            imaxscan98(FF, lane);                   // FF[k] = start of equal-CDF run
        } else if (t >= 64 && t < 64 + NW) {
            // distortion loss, concurrent with prep warps
            int n = t - 64;
            float midn = 0.5f * (s_s[n + 1] + s_s[n]);
            float inner = 0.0f;
#pragma unroll
            for (int m = 0; m < NW; m++) {
                float midm = 0.5f * (s_s[m + 1] + s_s[m]);
                inner += s_w[m] * fabsf(midn - midm);
            }
            float ds = s_s[n + 1] - s_s[n];
            pdist = s_w[n] * inner + s_w[n] * s_w[n] * ds * (1.0f / 3.0f);
        } else if (wid == 4 && lane < 3) {
            float dd = pd[r * 3 + lane] - gt[r * 3 + lane];
            prgb = dd * dd;
        }
        __syncthreads();   // blur tables ready

        for (int q = t; q < P0; q += 256)
            itp0[q] = interp_q(ps0[r * P0 + q], Bb[0], Wb[0], Cb[0], FFb[0]);
        for (int q = t; q < P1; q += 256)
            itp1[q] = interp_q(ps1[r * P1 + q], Bb[1], Wb[1], Cb[1], FFb[1]);
        __syncthreads();

        float li0 = 0.0f, li1 = 0.0f;
        for (int q = t; q < P0 - 1; q += 256) {
            float ws  = itp0[q + 1] - itp0[q];
            float pwv = pw0[r * (P0 - 1) + q];
            float dd = fmaxf(ws - pwv, 0.0f);
            li0 += dd * dd / (pwv + 1e-5f);
        }
        for (int q = t; q < P1 - 1; q += 256) {
            float ws  = itp1[q + 1] - itp1[q];
            float pwv = pw1[r * (P1 - 1) + q];
            float dd = fmaxf(ws - pwv, 0.0f);
            li1 += dd * dd / (pwv + 1e-5f);
        }
#pragma unroll
        for (int o = 16; o > 0; o >>= 1) {
            prgb  += __shfl_down_sync(0xffffffffu, prgb,  o);
            li0   += __shfl_down_sync(0xffffffffu, li0,   o);
            li1   += __shfl_down_sync(0xffffffffu, li1,   o);
            pdist += __shfl_down_sync(0xffffffffu, pdist, o);
        }
        if (lane == 0) {
            atomicAdd(&s_part[0], prgb);
            atomicAdd(&s_part[1], li0);
            atomicAdd(&s_part[2], li1);
            atomicAdd(&s_part[3], pdist);
        }
        __syncthreads();
        if (t == 0) {
            atomicAdd(&g_acc[0], (double)s_part[0]);
            atomicAdd(&g_acc[1], (double)s_part[1]);
            atomicAdd(&g_acc[2], (double)s_part[2]);
            atomicAdd(&g_acc[3], (double)s_part[3]);
        }
    }

    // ───────────────── last-block finalizer (reads, writes out, resets state) ─────────────────
    if (t == 0) {
        __threadfence();
        unsigned tk = atomicAdd(&g_ticket, 1u);
        if (tk == gridDim.x - 1) {
            volatile double* a = g_acc;   // L1-bypassing reads; all blocks fenced before ticket
            double loss = a[0] / ((double)R * 3.0)
                        + a[1] / ((double)R * 256.0)
                        + a[2] / ((double)R * 96.0)
                        + 0.01 * a[3] / (double)R
                        + 0.1 * (a[4] + a[5]) / (65536.0 * 2.0);
            out[0] = (float)loss;
#pragma unroll
            for (int i = 0; i < 6; i++) g_acc[i] = 0.0;
            __threadfence();
            g_ticket = 0;                 // ready for next graph replay
        }
    }
}

extern "C" void kernel_launch(void* const* d_in, const int* in_sizes, int n_in,
                              void* d_out, int out_size) {
    const float* pd    = (const float*)d_in[0];
    const float* gt    = (const float*)d_in[1];
    const float* sdist = (const float*)d_in[2];
    const float* wts   = (const float*)d_in[3];
    const float* ps0   = (const float*)d_in[4];
    const float* pw0   = (const float*)d_in[5];
    const float* ps1   = (const float*)d_in[6];
    const float* pw1   = (const float*)d_in[7];
    const float* e0    = (const float*)d_in[8];
    const float* e1    = (const float*)d_in[9];
    const int*   ix0   = (const int*)d_in[10];
    const int*   ix1   = (const int*)d_in[11];

    int R = in_sizes[0] / 3;        // 4096
    int M = in_sizes[8] / 2;        // 196608
    int HB = (M + 255) / 256;       // hash blocks first: latency-bound, overlaps ray compute

    fused_kernel<<<HB + R, 256>>>(pd, gt, sdist, wts, ps0, pw0, ps1, pw1,
                                  e0, e1, ix0, ix1, R, M, HB, (float*)d_out);
}

// round 9
// speedup vs baseline: 3.1502x; 1.0483x over previous
#include <cuda_runtime.h>

#define NPT 49    // N+1 render sdist points
#define NW  48    // N render weights
#define PB  98    // 2N+2 blur bounds
#define P0  257   // prop level 0 sdist points
#define P1  97    // prop level 1 sdist points

// accumulators: [0]=rgb, [1]=inter0, [2]=inter1, [3]=dist, [4]=hash0, [5]=hash1
__device__ double g_acc[6];          // zero-init at load; reset by finalizer each run
__device__ unsigned int g_ticket;

__device__ __forceinline__ float wexscan_add(float v, int lane) {
    float x = v;
#pragma unroll
    for (int o = 1; o < 32; o <<= 1) {
        float y = __shfl_up_sync(0xffffffffu, x, o);
        if (lane >= o) x += y;
    }
    return x - v;
}

// inclusive in-place +scan of a[0..97] by one warp (4 contiguous elems per lane)
__device__ __forceinline__ void iscan98(float* a, int lane) {
    const int base = lane << 2;
    float v[4];
#pragma unroll
    for (int i = 0; i < 4; i++) { int k = base + i; v[i] = (k < PB) ? a[k] : 0.0f; }
    float s = 0.0f;
#pragma unroll
    for (int i = 0; i < 4; i++) { s += v[i]; v[i] = s; }
    float off = wexscan_add(s, lane);
#pragma unroll
    for (int i = 0; i < 4; i++) { int k = base + i; if (k < PB) a[k] = v[i] + off; }
    __syncwarp();
}

// inclusive in-place max-scan of int a[0..97] by one warp
__device__ __forceinline__ void imaxscan98(int* a, int lane) {
    const int base = lane << 2;
    int v[4];
#pragma unroll
    for (int i = 0; i < 4; i++) { int k = base + i; v[i] = (k < PB) ? a[k] : 0; }
    int loc = 0;
#pragma unroll
    for (int i = 0; i < 4; i++) { loc = max(loc, v[i]); v[i] = loc; }
    int inc = loc;
#pragma unroll
    for (int o = 1; o < 32; o <<= 1) {
        int y = __shfl_up_sync(0xffffffffu, inc, o);
        if (lane >= o) inc = max(inc, y);
    }
    int exc = __shfl_up_sync(0xffffffffu, inc, 1);
    if (lane == 0) exc = 0;
#pragma unroll
    for (int i = 0; i < 4; i++) { int k = base + i; if (k < PB) a[k] = max(v[i], exc); }
    __syncwarp();
}

// sorted_interp_quad per-query semantics; i0 tie-search via precomputed FF[]
__device__ __forceinline__ float interp_q(float x, const float* __restrict__ B,
                                          const float* __restrict__ W,
                                          const float* __restrict__ C,
                                          const int* __restrict__ FF) {
    int lo = 0, hi = PB;
    while (lo < hi) { int m = (lo + hi) >> 1; if (B[m] <= x) lo = m + 1; else hi = m; }
    int pl = lo - 1;
    float xp0, f0, fp0;
    if (pl < 0) { xp0 = B[0]; f0 = C[0]; fp0 = W[0]; }
    else { xp0 = B[pl]; f0 = C[pl]; fp0 = W[FF[pl]]; }
    float xp1, fp1;
    if (pl == PB - 1) { xp1 = B[PB - 1]; fp1 = W[0]; }
    else {
        int pf = pl + 1;
        xp1 = B[pf];
        fp1 = (pl >= 0 && C[PB - 1] == C[pf]) ? W[0] : W[pf];
    }
    float num = x - xp0, den = xp1 - xp0;
    float off = (den != 0.0f) ? num / den : ((num > 0.0f) ? 1.0f : 0.0f);
    off = fminf(fmaxf(off, 0.0f), 1.0f);
    return f0 + num * (fp0 + fp1 * off + fp0 * (1.0f - off)) * 0.5f;
}

__global__ __launch_bounds__(256) void fused_kernel(
    const float* __restrict__ pd, const float* __restrict__ gt,
    const float* __restrict__ sdist, const float* __restrict__ wts,
    const float* __restrict__ ps0, const float* __restrict__ pw0,
    const float* __restrict__ ps1, const float* __restrict__ pw1,
    const float* __restrict__ e0, const float* __restrict__ e1,
    const int* __restrict__ ix0, const int* __restrict__ ix1,
    int R, int M, int HB, float* __restrict__ out)
{
    __shared__ float s_s[NPT], s_w[NW], s_wn[NW];
    __shared__ float Bb[2][PB], Wb[2][PB], Cb[2][PB], Tb[2][PB];
    __shared__ int   FFb[2][PB];
    __shared__ float itp0[P0], itp1[P1];
    __shared__ float s_q0[P0], s_q1[P1], s_pw0[P0 - 1], s_pw1[P1 - 1];
    __shared__ float s_part[4];

    const int bid = blockIdx.x;
    const int t = threadIdx.x;
    const int lane = t & 31;
    const int wid = t >> 5;

    if (t < 4) s_part[t] = 0.0f;

    if (bid < HB) {
        // ───────── hash decay: run-scan over sorted indices ─────────
        int g = bid * 256 + t;
        float c0 = 0.0f, c1 = 0.0f;
        if (g < M) {
            int v = ix0[g];
            if (g == 0 || ix0[g - 1] != v) {
                float sum = 0.0f; int cnt = 0; int j = g;
                while (j < M && ix0[j] == v) {
                    float2 e = reinterpret_cast<const float2*>(e0)[j];
                    sum += e.x * e.x + e.y * e.y; cnt++; j++;
                }
                c0 = sum / (float)cnt;
            }
            v = ix1[g];
            if (g == 0 || ix1[g - 1] != v) {
                float sum = 0.0f; int cnt = 0; int j = g;
                while (j < M && ix1[j] == v) {
                    float2 e = reinterpret_cast<const float2*>(e1)[j];
                    sum += e.x * e.x + e.y * e.y; cnt++; j++;
                }
                c1 = sum / (float)cnt;
            }
        }
#pragma unroll
        for (int o = 16; o > 0; o >>= 1) {
            c0 += __shfl_down_sync(0xffffffffu, c0, o);
            c1 += __shfl_down_sync(0xffffffffu, c1, o);
        }
        __syncthreads();
        if (lane == 0) { atomicAdd(&s_part[0], c0); atomicAdd(&s_part[1], c1); }
        __syncthreads();
        if (t == 0) {
            atomicAdd(&g_acc[4], (double)s_part[0]);
            atomicAdd(&g_acc[5], (double)s_part[1]);
        }
    } else {
        // ───────── per-ray losses ─────────
        const int r = bid - HB;
        if (t < NPT) s_s[t] = sdist[r * NPT + t];
        if (t < NW)  s_w[t] = wts[r * NW + t];
        __syncthreads();
        if (t < NW) s_wn[t] = s_w[t] / (s_s[t + 1] - s_s[t] + 1e-8f);
        __syncthreads();

        float pdist = 0.0f, prgb = 0.0f;
        if (wid < 2) {
            // blur_step_function + CDF, one warp per pulse level
            const int lvl = wid;
            const float pw = lvl ? 0.005f : 0.01f;
            const float inv2 = 1.0f / (2.0f * pw);
            float* B = Bb[lvl]; float* T = Tb[lvl]; float* W = Wb[lvl];
            float* C = Cb[lvl]; int* FF = FFb[lvl];

            // scatter by stable-merge rank (exact sort-key comparisons)
#pragma unroll
            for (int rep = 0; rep < 2; rep++) {
                int i = lane + rep * 32;
                if (i < NPT) {
                    float si = s_s[i];
                    float d = ((i < NW) ? s_wn[i] : 0.0f) - ((i > 0) ? s_wn[i - 1] : 0.0f);
                    float rd = d * inv2;
                    float av = si - pw;
                    int lo = 0, hi = NPT;   // #B strictly before
                    while (lo < hi) { int m = (lo + hi) >> 1; if (s_s[m] + pw < av) lo = m + 1; else hi = m; }
                    int ra = i + lo;
                    B[ra] = av; T[ra] = rd;
                    float bv = si + pw;
                    lo = 0; hi = NPT;       // #A at-or-before
                    while (lo < hi) { int m = (lo + hi) >> 1; if (s_s[m] - pw <= bv) lo = m + 1; else hi = m; }
                    int rb = i + lo;
                    B[rb] = bv; T[rb] = -rd;
                }
            }
            __syncwarp();
            iscan98(T, lane);                       // cumsum(radio_sorted)
            {
                const int base = lane << 2;
#pragma unroll
                for (int i2 = 0; i2 < 4; i2++) {
                    int k = base + i2;
                    if (k < PB - 1) T[k] = (B[k + 1] - B[k]) * T[k];
                    else if (k == PB - 1) T[k] = 0.0f;
                }
            }
            __syncwarp();
            iscan98(T, lane);                       // cumsum(ds * c)
            {
                const int base = lane << 2;
#pragma unroll
                for (int i2 = 0; i2 < 4; i2++) {
                    int k = base + i2;
                    if (k < PB) W[k] = (k == 0) ? 0.0f : fmaxf(T[k - 1], 0.0f);
                }
            }
            __syncwarp();
            {
                const int base = lane << 2;
#pragma unroll
                for (int i2 = 0; i2 < 4; i2++) {
                    int k = base + i2;
                    if (k < PB - 1) T[k] = 0.5f * (W[k + 1] + W[k]) * (B[k + 1] - B[k]);
                    else if (k == PB - 1) T[k] = 0.0f;
                }
            }
            __syncwarp();
            iscan98(T, lane);                       // cumulative trapezoid area
            {
                const int base = lane << 2;
#pragma unroll
                for (int i2 = 0; i2 < 4; i2++) {
                    int k = base + i2;
                    if (k < PB) C[k] = (k == 0) ? 0.0f : T[k - 1];
                }
            }
            __syncwarp();
            {
                const int base = lane << 2;
#pragma unroll
                for (int i2 = 0; i2 < 4; i2++) {
                    int k = base + i2;
                    if (k < PB) FF[k] = (k == 0 || C[k] != C[k - 1]) ? k : 0;
                }
            }
            __syncwarp();
            imaxscan98(FF, lane);
        } else if (wid == 2) {
            // distortion loss O(N) via sorted-mid prefix sums; rgb on lanes 24-26
            float pdv = 0.0f, gtv = 0.0f;
            if (lane >= 24 && lane < 27) {          // issue rgb loads early
                pdv = pd[r * 3 + lane - 24];
                gtv = gt[r * 3 + lane - 24];
            }
            float w0 = 0, w1 = 0, m0 = 0, m1 = 0, ds0 = 0, ds1 = 0;
            if (lane < 24) {
                int k0 = lane * 2;
                float a = s_s[k0], b = s_s[k0 + 1], c = s_s[k0 + 2];
                w0 = s_w[k0]; w1 = s_w[k0 + 1];
                m0 = 0.5f * (a + b); m1 = 0.5f * (b + c);
                ds0 = b - a; ds1 = c - b;
            }
            float lw = w0 + w1, lb = w0 * m0 + w1 * m1;
            float iw = lw, ib = lb;
#pragma unroll
            for (int o = 1; o < 32; o <<= 1) {
                float yw = __shfl_up_sync(0xffffffffu, iw, o);
                float yb = __shfl_up_sync(0xffffffffu, ib, o);
                if (lane >= o) { iw += yw; ib += yb; }
            }
            float At = __shfl_sync(0xffffffffu, iw, 31);
            float Bt = __shfl_sync(0xffffffffu, ib, 31);
            float Ew = iw - lw, Eb = ib - lb;
            float A0 = Ew + w0, A1 = A0 + w1;
            float Bp0 = Eb + w0 * m0, Bp1 = Bp0 + w1 * m1;
            // sum_m w_m|mid_k - mid_m| = mid_k*(2A_k - At) + Bt - 2B_k  (mids ascending)
            pdist = w0 * (m0 * (2.0f * A0 - At) + Bt - 2.0f * Bp0) + w0 * w0 * ds0 * (1.0f / 3.0f)
                  + w1 * (m1 * (2.0f * A1 - At) + Bt - 2.0f * Bp1) + w1 * w1 * ds1 * (1.0f / 3.0f);
            if (lane >= 24 && lane < 27) { float dd = pdv - gtv; prgb = dd * dd; }
        } else {
            // warps 3-7: prefetch query/weight arrays into smem (hides GMEM latency)
            for (int i = t - 96; i < 706; i += 160) {
                if (i < 257)      s_q0[i]        = ps0[r * P0 + i];
                else if (i < 354) s_q1[i - 257]  = ps1[r * P1 + (i - 257)];
                else if (i < 610) s_pw0[i - 354] = pw0[r * (P0 - 1) + (i - 354)];
                else              s_pw1[i - 610] = pw1[r * (P1 - 1) + (i - 610)];
            }
        }
        __syncthreads();   // blur tables + prefetched queries ready

        // balanced searches: every thread 1, threads 0..97 do a second
        itp0[t] = interp_q(s_q0[t], Bb[0], Wb[0], Cb[0], FFb[0]);
        if (t == 0) itp0[256] = interp_q(s_q0[256], Bb[0], Wb[0], Cb[0], FFb[0]);
        if (t >= 1 && t < 98) itp1[t - 1] = interp_q(s_q1[t - 1], Bb[1], Wb[1], Cb[1], FFb[1]);
        __syncthreads();

        float li0, li1 = 0.0f;
        {
            float ws  = itp0[t + 1] - itp0[t];
            float pwv = s_pw0[t];
            float dd = fmaxf(ws - pwv, 0.0f);
            li0 = dd * dd / (pwv + 1e-5f);
        }
        if (t < 96) {
            float ws  = itp1[t + 1] - itp1[t];
            float pwv = s_pw1[t];
            float dd = fmaxf(ws - pwv, 0.0f);
            li1 = dd * dd / (pwv + 1e-5f);
        }
#pragma unroll
        for (int o = 16; o > 0; o >>= 1) {
            prgb  += __shfl_down_sync(0xffffffffu, prgb,  o);
            li0   += __shfl_down_sync(0xffffffffu, li0,   o);
            li1   += __shfl_down_sync(0xffffffffu, li1,   o);
            pdist += __shfl_down_sync(0xffffffffu, pdist, o);
        }
        if (lane == 0) {
            atomicAdd(&s_part[0], prgb);
            atomicAdd(&s_part[1], li0);
            atomicAdd(&s_part[2], li1);
            atomicAdd(&s_part[3], pdist);
        }
        __syncthreads();
        if (t == 0) {
            atomicAdd(&g_acc[0], (double)s_part[0]);
            atomicAdd(&g_acc[1], (double)s_part[1]);
            atomicAdd(&g_acc[2], (double)s_part[2]);
            atomicAdd(&g_acc[3], (double)s_part[3]);
        }
    }

    // ───────── last-block finalizer ─────────
    if (t == 0) {
        __threadfence();
        unsigned tk = atomicAdd(&g_ticket, 1u);
        if (tk == gridDim.x - 1) {
            volatile double* a = g_acc;
            double loss = a[0] / ((double)R * 3.0)
                        + a[1] / ((double)R * 256.0)
                        + a[2] / ((double)R * 96.0)
                        + 0.01 * a[3] / (double)R
                        + 0.1 * (a[4] + a[5]) / (65536.0 * 2.0);
            out[0] = (float)loss;
#pragma unroll
            for (int i = 0; i < 6; i++) g_acc[i] = 0.0;
            __threadfence();
            g_ticket = 0;
        }
    }
}

extern "C" void kernel_launch(void* const* d_in, const int* in_sizes, int n_in,
                              void* d_out, int out_size) {
    const float* pd    = (const float*)d_in[0];
    const float* gt    = (const float*)d_in[1];
    const float* sdist = (const float*)d_in[2];
    const float* wts   = (const float*)d_in[3];
    const float* ps0   = (const float*)d_in[4];
    const float* pw0   = (const float*)d_in[5];
    const float* ps1   = (const float*)d_in[6];
    const float* pw1   = (const float*)d_in[7];
    const float* e0    = (const float*)d_in[8];
    const float* e1    = (const float*)d_in[9];
    const int*   ix0   = (const int*)d_in[10];
    const int*   ix1   = (const int*)d_in[11];

    int R = in_sizes[0] / 3;        // 4096
    int M = in_sizes[8] / 2;        // 196608
    int HB = (M + 255) / 256;       // hash blocks first (latency-bound, overlap ray compute)

    fused_kernel<<<HB + R, 256>>>(pd, gt, sdist, wts, ps0, pw0, ps1, pw1,
                                  e0, e1, ix0, ix1, R, M, HB, (float*)d_out);
}

// round 10
// speedup vs baseline: 3.1721x; 1.0069x over previous
#include <cuda_runtime.h>

#define NPT 49    // N+1 render sdist points
#define NW  48    // N render weights
#define PB  98    // 2N+2 blur bounds
#define P0  257   // prop level 0 sdist points
#define P1  97    // prop level 1 sdist points
#define NBK 96    // LUT buckets per level

// accumulators: [0]=rgb, [1]=inter0, [2]=inter1, [3]=dist, [4]=hash0, [5]=hash1
__device__ double g_acc[6];          // zero-init at load; reset by finalizer each run
__device__ unsigned int g_ticket;

__device__ __forceinline__ float wexscan_add(float v, int lane) {
    float x = v;
#pragma unroll
    for (int o = 1; o < 32; o <<= 1) {
        float y = __shfl_up_sync(0xffffffffu, x, o);
        if (lane >= o) x += y;
    }
    return x - v;
}

// inclusive in-place +scan of a[0..97] by one warp (4 contiguous elems per lane)
__device__ __forceinline__ void iscan98(float* a, int lane) {
    const int base = lane << 2;
    float v[4];
#pragma unroll
    for (int i = 0; i < 4; i++) { int k = base + i; v[i] = (k < PB) ? a[k] : 0.0f; }
    float s = 0.0f;
#pragma unroll
    for (int i = 0; i < 4; i++) { s += v[i]; v[i] = s; }
    float off = wexscan_add(s, lane);
#pragma unroll
    for (int i = 0; i < 4; i++) { int k = base + i; if (k < PB) a[k] = v[i] + off; }
    __syncwarp();
}

// inclusive in-place max-scan of int a[0..97] by one warp
__device__ __forceinline__ void imaxscan98(int* a, int lane) {
    const int base = lane << 2;
    int v[4];
#pragma unroll
    for (int i = 0; i < 4; i++) { int k = base + i; v[i] = (k < PB) ? a[k] : 0; }
    int loc = 0;
#pragma unroll
    for (int i = 0; i < 4; i++) { loc = max(loc, v[i]); v[i] = loc; }
    int inc = loc;
#pragma unroll
    for (int o = 1; o < 32; o <<= 1) {
        int y = __shfl_up_sync(0xffffffffu, inc, o);
        if (lane >= o) inc = max(inc, y);
    }
    int exc = __shfl_up_sync(0xffffffffu, inc, 1);
    if (lane == 0) exc = 0;
#pragma unroll
    for (int i = 0; i < 4; i++) { int k = base + i; if (k < PB) a[k] = max(v[i], exc); }
    __syncwarp();
}

// sorted_interp_quad with bucket-LUT accelerated search.
// Guard loops (fwd+back) make LUT rounding slop harmless: pl is exact.
__device__ __forceinline__ float interp_lut(float x, const float* __restrict__ B,
                                            const float* __restrict__ W,
                                            const float* __restrict__ C,
                                            const int* __restrict__ FF,
                                            const int* __restrict__ LUT,
                                            float blo, float bscale) {
    int j = (int)((x - blo) * bscale);
    j = min(NBK - 1, max(0, j));
    int c = LUT[j];
    while (c < PB && B[c] <= x) c++;
    while (c > 0 && B[c - 1] > x) c--;
    int pl = c - 1;

    float xp0, f0, fp0;
    if (pl < 0) { xp0 = B[0]; f0 = C[0]; fp0 = W[0]; }
    else { xp0 = B[pl]; f0 = C[pl]; fp0 = W[FF[pl]]; }
    float xp1, fp1;
    if (pl == PB - 1) { xp1 = B[PB - 1]; fp1 = W[0]; }
    else {
        int pf = pl + 1;
        xp1 = B[pf];
        fp1 = (pl >= 0 && C[PB - 1] == C[pf]) ? W[0] : W[pf];
    }
    float num = x - xp0, den = xp1 - xp0;
    float off = (den != 0.0f) ? num / den : ((num > 0.0f) ? 1.0f : 0.0f);
    off = fminf(fmaxf(off, 0.0f), 1.0f);
    return f0 + num * (fp0 + fp1 * off + fp0 * (1.0f - off)) * 0.5f;
}

__global__ __launch_bounds__(256) void fused_kernel(
    const float* __restrict__ pd, const float* __restrict__ gt,
    const float* __restrict__ sdist, const float* __restrict__ wts,
    const float* __restrict__ ps0, const float* __restrict__ pw0,
    const float* __restrict__ ps1, const float* __restrict__ pw1,
    const float* __restrict__ e0, const float* __restrict__ e1,
    const int* __restrict__ ix0, const int* __restrict__ ix1,
    int R, int M, int HB, float* __restrict__ out)
{
    __shared__ float s_s[NPT], s_w[NW];
    __shared__ float Bb[2][PB], Wb[2][PB], Cb[2][PB], Tb[2][PB];
    __shared__ int   FFb[2][PB];
    __shared__ int   LUTb[2][NBK];
    __shared__ float s_lo[2], s_scale[2];
    __shared__ float itp0[P0], itp1[P1];
    __shared__ float s_part[4];

    const int bid = blockIdx.x;
    const int t = threadIdx.x;
    const int lane = t & 31;
    const int wid = t >> 5;

    if (t < 4) s_part[t] = 0.0f;

    if (bid < HB) {
        // ───────── hash decay: run-scan over sorted indices ─────────
        int g = bid * 256 + t;
        float c0 = 0.0f, c1 = 0.0f;
        if (g < M) {
            int v = ix0[g];
            if (g == 0 || ix0[g - 1] != v) {
                float sum = 0.0f; int cnt = 0; int j = g;
                while (j < M && ix0[j] == v) {
                    float2 e = reinterpret_cast<const float2*>(e0)[j];
                    sum += e.x * e.x + e.y * e.y; cnt++; j++;
                }
                c0 = sum / (float)cnt;
            }
            v = ix1[g];
            if (g == 0 || ix1[g - 1] != v) {
                float sum = 0.0f; int cnt = 0; int j = g;
                while (j < M && ix1[j] == v) {
                    float2 e = reinterpret_cast<const float2*>(e1)[j];
                    sum += e.x * e.x + e.y * e.y; cnt++; j++;
                }
                c1 = sum / (float)cnt;
            }
        }
#pragma unroll
        for (int o = 16; o > 0; o >>= 1) {
            c0 += __shfl_down_sync(0xffffffffu, c0, o);
            c1 += __shfl_down_sync(0xffffffffu, c1, o);
        }
        __syncthreads();
        if (lane == 0) { atomicAdd(&s_part[0], c0); atomicAdd(&s_part[1], c1); }
        __syncthreads();
        if (t == 0) {
            atomicAdd(&g_acc[4], (double)s_part[0]);
            atomicAdd(&g_acc[5], (double)s_part[1]);
        }
    } else {
        // ───────── per-ray losses ─────────
        const int r = bid - HB;

        // register-resident query/weight loads: issued NOW, consumed 2 barriers later
        float x0  = ps0[r * P0 + t];
        float x0e = (t == 0) ? ps0[r * P0 + 256] : 0.0f;
        float x1  = (t >= 1 && t < 98) ? ps1[r * P1 + t - 1] : 0.0f;
        float pv0 = pw0[r * (P0 - 1) + t];
        float pv1 = (t < 96) ? pw1[r * (P1 - 1) + t] : 0.0f;

        if (t < NPT) s_s[t] = sdist[r * NPT + t];
        if (t < NW)  s_w[t] = wts[r * NW + t];
        __syncthreads();

        float pdist = 0.0f, prgb = 0.0f;
        if (wid < 2) {
            // phase1: scatter blur bounds by stable-merge rank (wn computed inline)
            const int lvl = wid;
            const float pw = lvl ? 0.005f : 0.01f;
            const float inv2 = 1.0f / (2.0f * pw);
            float* B = Bb[lvl]; float* T = Tb[lvl];
#pragma unroll
            for (int rep = 0; rep < 2; rep++) {
                int i = lane + rep * 32;
                if (i < NPT) {
                    float si = s_s[i];
                    float wn_i   = (i < NW) ? s_w[i]     / (s_s[i + 1] - si        + 1e-8f) : 0.0f;
                    float wn_im1 = (i > 0)  ? s_w[i - 1] / (si         - s_s[i - 1] + 1e-8f) : 0.0f;
                    float rd = (wn_i - wn_im1) * inv2;
                    float av = si - pw;
                    int lo = 0, hi = NPT;   // #B strictly before
                    while (lo < hi) { int m = (lo + hi) >> 1; if (s_s[m] + pw < av) lo = m + 1; else hi = m; }
                    int ra = i + lo;
                    B[ra] = av; T[ra] = rd;
                    float bv = si + pw;
                    lo = 0; hi = NPT;       // #A at-or-before
                    while (lo < hi) { int m = (lo + hi) >> 1; if (s_s[m] - pw <= bv) lo = m + 1; else hi = m; }
                    int rb = i + lo;
                    B[rb] = bv; T[rb] = -rd;
                }
            }
        } else if (wid == 2) {
            // phase1: distortion O(N) via sorted-mid prefix sums; rgb on lanes 24-26
            float pdv = 0.0f, gtv = 0.0f;
            if (lane >= 24 && lane < 27) {
                pdv = pd[r * 3 + lane - 24];
                gtv = gt[r * 3 + lane - 24];
            }
            float w0 = 0, w1 = 0, m0 = 0, m1 = 0, ds0 = 0, ds1 = 0;
            if (lane < 24) {
                int k0 = lane * 2;
                float a = s_s[k0], b = s_s[k0 + 1], c = s_s[k0 + 2];
                w0 = s_w[k0]; w1 = s_w[k0 + 1];
                m0 = 0.5f * (a + b); m1 = 0.5f * (b + c);
                ds0 = b - a; ds1 = c - b;
            }
            float lw = w0 + w1, lb = w0 * m0 + w1 * m1;
            float iw = lw, ib = lb;
#pragma unroll
            for (int o = 1; o < 32; o <<= 1) {
                float yw = __shfl_up_sync(0xffffffffu, iw, o);
                float yb = __shfl_up_sync(0xffffffffu, ib, o);
                if (lane >= o) { iw += yw; ib += yb; }
            }
            float At = __shfl_sync(0xffffffffu, iw, 31);
            float Bt = __shfl_sync(0xffffffffu, ib, 31);
            float Ew = iw - lw, Eb = ib - lb;
            float A0 = Ew + w0, A1 = A0 + w1;
            float Bp0 = Eb + w0 * m0, Bp1 = Bp0 + w1 * m1;
            pdist = w0 * (m0 * (2.0f * A0 - At) + Bt - 2.0f * Bp0) + w0 * w0 * ds0 * (1.0f / 3.0f)
                  + w1 * (m1 * (2.0f * A1 - At) + Bt - 2.0f * Bp1) + w1 * w1 * ds1 * (1.0f / 3.0f);
            if (lane >= 24 && lane < 27) { float dd = pdv - gtv; prgb = dd * dd; }
        }
        __syncthreads();   // B,T complete

        if (wid < 2) {
            // phase2: scans → W, C, FF  (one warp per level)
            const int lvl = wid;
            float* B = Bb[lvl]; float* T = Tb[lvl]; float* W = Wb[lvl];
            float* C = Cb[lvl]; int* FF = FFb[lvl];
            iscan98(T, lane);                       // cumsum(radio_sorted)
            {
                const int base = lane << 2;
#pragma unroll
                for (int i2 = 0; i2 < 4; i2++) {
                    int k = base + i2;
                    if (k < PB - 1) T[k] = (B[k + 1] - B[k]) * T[k];
                    else if (k == PB - 1) T[k] = 0.0f;
                }
            }
            __syncwarp();
            iscan98(T, lane);                       // cumsum(ds * c)
            {
                const int base = lane << 2;
#pragma unroll
                for (int i2 = 0; i2 < 4; i2++) {
                    int k = base + i2;
                    if (k < PB) W[k] = (k == 0) ? 0.0f : fmaxf(T[k - 1], 0.0f);
                }
            }
            __syncwarp();
            {
                const int base = lane << 2;
#pragma unroll
                for (int i2 = 0; i2 < 4; i2++) {
                    int k = base + i2;
                    if (k < PB - 1) T[k] = 0.5f * (W[k + 1] + W[k]) * (B[k + 1] - B[k]);
                    else if (k == PB - 1) T[k] = 0.0f;
                }
            }
            __syncwarp();
            iscan98(T, lane);                       // cumulative trapezoid area
            {
                const int base = lane << 2;
#pragma unroll
                for (int i2 = 0; i2 < 4; i2++) {
                    int k = base + i2;
                    if (k < PB) C[k] = (k == 0) ? 0.0f : T[k - 1];
                }
            }
            __syncwarp();
            {
                const int base = lane << 2;
#pragma unroll
                for (int i2 = 0; i2 < 4; i2++) {
                    int k = base + i2;
                    if (k < PB) FF[k] = (k == 0 || C[k] != C[k - 1]) ? k : 0;
                }
            }
            __syncwarp();
            imaxscan98(FF, lane);
        } else {
            // phase2: warps 2-7 (192 threads) build per-level 96-bucket LUTs
            int j = t - 64;                 // 0..191
            int lvl = (j >= NBK) ? 1 : 0;
            int b = j - lvl * NBK;
            const float* B = Bb[lvl];
            float blo = B[0], bhi = B[PB - 1];
            if (b == 0) { s_lo[lvl] = blo; s_scale[lvl] = (float)NBK / (bhi - blo); }
            float left = blo + (bhi - blo) * ((float)b * (1.0f / (float)NBK));
            int lo = 0, hi = PB;            // first k with B[k] >= left
            while (lo < hi) { int m = (lo + hi) >> 1; if (B[m] < left) lo = m + 1; else hi = m; }
            LUTb[lvl][b] = lo;
        }
        __syncthreads();   // tables + LUT ready

        itp0[t] = interp_lut(x0, Bb[0], Wb[0], Cb[0], FFb[0], LUTb[0], s_lo[0], s_scale[0]);
        if (t == 0)
            itp0[256] = interp_lut(x0e, Bb[0], Wb[0], Cb[0], FFb[0], LUTb[0], s_lo[0], s_scale[0]);
        if (t >= 1 && t < 98)
            itp1[t - 1] = interp_lut(x1, Bb[1], Wb[1], Cb[1], FFb[1], LUTb[1], s_lo[1], s_scale[1]);
        __syncthreads();

        float li0, li1 = 0.0f;
        {
            float ws = itp0[t + 1] - itp0[t];
            float dd = fmaxf(ws - pv0, 0.0f);
            li0 = dd * dd / (pv0 + 1e-5f);
        }
        if (t < 96) {
            float ws = itp1[t + 1] - itp1[t];
            float dd = fmaxf(ws - pv1, 0.0f);
            li1 = dd * dd / (pv1 + 1e-5f);
        }
#pragma unroll
        for (int o = 16; o > 0; o >>= 1) {
            prgb  += __shfl_down_sync(0xffffffffu, prgb,  o);
            li0   += __shfl_down_sync(0xffffffffu, li0,   o);
            li1   += __shfl_down_sync(0xffffffffu, li1,   o);
            pdist += __shfl_down_sync(0xffffffffu, pdist, o);
        }
        if (lane == 0) {
            atomicAdd(&s_part[0], prgb);
            atomicAdd(&s_part[1], li0);
            atomicAdd(&s_part[2], li1);
            atomicAdd(&s_part[3], pdist);
        }
        __syncthreads();
        if (t == 0) {
            atomicAdd(&g_acc[0], (double)s_part[0]);
            atomicAdd(&g_acc[1], (double)s_part[1]);
            atomicAdd(&g_acc[2], (double)s_part[2]);
            atomicAdd(&g_acc[3], (double)s_part[3]);
        }
    }

    // ───────── last-block finalizer ─────────
    if (t == 0) {
        __threadfence();
        unsigned tk = atomicAdd(&g_ticket, 1u);
        if (tk == gridDim.x - 1) {
            volatile double* a = g_acc;
            double loss = a[0] / ((double)R * 3.0)
                        + a[1] / ((double)R * 256.0)
                        + a[2] / ((double)R * 96.0)
                        + 0.01 * a[3] / (double)R
                        + 0.1 * (a[4] + a[5]) / (65536.0 * 2.0);
            out[0] = (float)loss;
#pragma unroll
            for (int i = 0; i < 6; i++) g_acc[i] = 0.0;
            __threadfence();
            g_ticket = 0;
        }
    }
}

extern "C" void kernel_launch(void* const* d_in, const int* in_sizes, int n_in,
                              void* d_out, int out_size) {
    const float* pd    = (const float*)d_in[0];
    const float* gt    = (const float*)d_in[1];
    const float* sdist = (const float*)d_in[2];
    const float* wts   = (const float*)d_in[3];
    const float* ps0   = (const float*)d_in[4];
    const float* pw0   = (const float*)d_in[5];
    const float* ps1   = (const float*)d_in[6];
    const float* pw1   = (const float*)d_in[7];
    const float* e0    = (const float*)d_in[8];
    const float* e1    = (const float*)d_in[9];
    const int*   ix0   = (const int*)d_in[10];
    const int*   ix1   = (const int*)d_in[11];

    int R = in_sizes[0] / 3;        // 4096
    int M = in_sizes[8] / 2;        // 196608
    int HB = (M + 255) / 256;       // hash blocks first (latency-bound, overlap ray compute)

    fused_kernel<<<HB + R, 256>>>(pd, gt, sdist, wts, ps0, pw0, ps1, pw1,
                                  e0, e1, ix0, ix1, R, M, HB, (float*)d_out);
}